// round 16
// baseline (speedup 1.0000x reference)
#include <cuda_runtime.h>
#include <cstdint>

// Problem constants
#define M_DIM 8192
#define N_DIM 4096
#define K_DIM 4096

#define CTA_M 128
#define CTA_N 128
#define CTA_K 64
#define SSTRIDE 80   // 64B of K data + 16B pad -> conflict-free ldmatrix tiles

#define NSTAGES 4
#define STAGE_BYTES ((CTA_M + CTA_N) * SSTRIDE)   // 20480
#define SMEM_ALLOC (NSTAGES * STAGE_BYTES)        // 81920 (2 CTAs/SM: 160 KB)

// Static scratch for int32 -> int8 narrowed operands (allocation-free).
__device__ int8_t g_x8[(size_t)M_DIM * K_DIM];   // 32 MB
__device__ int8_t g_w8[(size_t)N_DIM * K_DIM];   // 16 MB

__device__ __forceinline__ void cp_async16(uint32_t s, const void* g) {
    asm volatile("cp.async.cg.shared.global [%0], [%1], 16;\n" :: "r"(s), "l"(g));
}

__device__ __forceinline__ void ldsm_x4(uint32_t& r0, uint32_t& r1,
                                        uint32_t& r2, uint32_t& r3, uint32_t addr) {
    asm volatile("ldmatrix.sync.aligned.m8n8.x4.shared.b16 {%0,%1,%2,%3}, [%4];"
                 : "=r"(r0), "=r"(r1), "=r"(r2), "=r"(r3) : "r"(addr));
}

__device__ __forceinline__ void mma_s8(int* c, const uint32_t* a, const uint32_t* b) {
    asm volatile(
        "mma.sync.aligned.m16n8k32.row.col.s32.s8.s8.s32 "
        "{%0,%1,%2,%3}, {%4,%5,%6,%7}, {%8,%9}, {%0,%1,%2,%3};\n"
        : "+r"(c[0]), "+r"(c[1]), "+r"(c[2]), "+r"(c[3])
        : "r"(a[0]), "r"(a[1]), "r"(a[2]), "r"(a[3]), "r"(b[0]), "r"(b[1]));
}

// ---- single fused int32 -> int8 narrowing pre-pass ----
__device__ __forceinline__ uint32_t pack4(int4 v) {
    return __byte_perm(__byte_perm((uint32_t)v.x, (uint32_t)v.y, 0x0040),
                       __byte_perm((uint32_t)v.z, (uint32_t)v.w, 0x0040), 0x5410);
}

#define X_VEC ((size_t)M_DIM * K_DIM / 16)   // 2097152 uint4-stores for X
#define W_VEC ((size_t)N_DIM * K_DIM / 16)   // 1048576 for W

__global__ __launch_bounds__(256)
void convert_kernel(const int* __restrict__ xs, const int* __restrict__ ws) {
    const size_t i = (size_t)blockIdx.x * blockDim.x + threadIdx.x;  // 16 elems each
    const int* src;
    uint4* dst;
    size_t idx;
    if (i < X_VEC) { src = xs; dst = reinterpret_cast<uint4*>(g_x8); idx = i; }
    else           { src = ws; dst = reinterpret_cast<uint4*>(g_w8); idx = i - X_VEC; }
    const int4* s4 = reinterpret_cast<const int4*>(src) + idx * 4;
    uint4 o;
    o.x = pack4(s4[0]); o.y = pack4(s4[1]); o.z = pack4(s4[2]); o.w = pack4(s4[3]);
    dst[idx] = o;
}

// ---- main GEMM: mma.sync m16n8k32.s8 + ldmatrix, 4-stage cp.async ----
// Stores RAW int32 accumulators into the output buffer (int32 view);
// the separate epilogue kernel transforms them in place.
__global__ __launch_bounds__(256, 2)
void w8a8_gemm_kernel(int* __restrict__ outI)
{
    extern __shared__ uint8_t smem[];

    const int8_t* __restrict__ X = g_x8;
    const int8_t* __restrict__ W = g_w8;

    const int tid   = threadIdx.x;
    const int warp  = tid >> 5;
    const int lane  = tid & 31;
    const int group = lane >> 2;   // 0..7
    const int tg    = lane & 3;    // 0..3
    const int wm    = warp >> 2;   // 0..1  (64 rows of M each)
    const int wn    = warp & 3;    // 0..3  (32 cols of N each)

    const int cta_n = blockIdx.x * CTA_N;
    const int cta_m = blockIdx.y * CTA_M;

    // Global-load mapping: 256 threads, each covers 2 rows x one 16B chunk per tile
    const int lr = tid >> 2;          // 0..63
    const int lc = (tid & 3) << 4;    // 0,16,32,48

    const int8_t* gA = X + (size_t)(cta_m + lr) * K_DIM + lc;
    const int8_t* gB = W + (size_t)(cta_n + lr) * K_DIM + lc;

    const uint32_t sBase = (uint32_t)__cvta_generic_to_shared(smem);
    const uint32_t dAl = (uint32_t)(lr * SSTRIDE + lc);
    const uint32_t dBl = (uint32_t)(CTA_M * SSTRIDE) + dAl;   // B after A within stage

    // ldmatrix per-lane offsets (verified layout, rel_err 0.0):
    const uint32_t aLdOff = (uint32_t)((wm * 64 + (lane & 15)) * SSTRIDE
                                       + (lane >> 4) * 16);
    const uint32_t bLdOff = (uint32_t)(CTA_M * SSTRIDE
                                       + (wn * 32 + ((lane >> 4) & 1) * 8 + (lane & 7)) * SSTRIDE
                                       + ((lane >> 3) & 1) * 16);

    int acc[4][4][4];
    #pragma unroll
    for (int i = 0; i < 4; ++i)
        #pragma unroll
        for (int j = 0; j < 4; ++j)
            #pragma unroll
            for (int r = 0; r < 4; ++r)
                acc[i][j][r] = 0;

    const int KITERS = K_DIM / CTA_K;   // 64

    // ---- prologue: load chunks 0..2 into stages 0..2 ----
    #pragma unroll
    for (int c = 0; c < NSTAGES - 1; ++c) {
        const uint32_t st = sBase + (uint32_t)(c * STAGE_BYTES);
        const int k0 = c * CTA_K;
        cp_async16(st + dAl, gA + k0);
        cp_async16(st + dAl + 64u * SSTRIDE, gA + (size_t)64 * K_DIM + k0);
        cp_async16(st + dBl, gB + k0);
        cp_async16(st + dBl + 64u * SSTRIDE, gB + (size_t)64 * K_DIM + k0);
        asm volatile("cp.async.commit_group;\n" ::);
    }

    for (int kit = 0; kit < KITERS; ++kit) {
        if (kit < KITERS - (NSTAGES - 1)) {
            asm volatile("cp.async.wait_group 2;\n" ::);
        } else {
            asm volatile("cp.async.wait_group 0;\n" ::);
        }
        // Single barrier per k-iter: proves (a) chunk kit's data visible to all,
        // (b) all warps finished reading stage kit-1, which the prefetch below
        // (slot (kit+3)&3 == (kit-1)&3) overwrites.
        __syncthreads();

        const uint32_t stage = sBase + (uint32_t)((kit & (NSTAGES - 1)) * STAGE_BYTES);

        // prefetch chunk kit+3
        const int kc = kit + (NSTAGES - 1);
        if (kc < KITERS) {
            const uint32_t st = sBase + (uint32_t)((kc & (NSTAGES - 1)) * STAGE_BYTES);
            const int k0 = kc * CTA_K;
            cp_async16(st + dAl, gA + k0);
            cp_async16(st + dAl + 64u * SSTRIDE, gA + (size_t)64 * K_DIM + k0);
            cp_async16(st + dBl, gB + k0);
            cp_async16(st + dBl + 64u * SSTRIDE, gB + (size_t)64 * K_DIM + k0);
            asm volatile("cp.async.commit_group;\n" ::);
        }

        #pragma unroll
        for (int kp = 0; kp < 2; ++kp) {       // two k=32 phases inside CTA_K=64
            uint32_t af[4][4];
            uint32_t bf[4][2];
            #pragma unroll
            for (int i = 0; i < 4; ++i)
                ldsm_x4(af[i][0], af[i][1], af[i][2], af[i][3],
                        stage + aLdOff + (uint32_t)(i * 16 * SSTRIDE + kp * 32));
            #pragma unroll
            for (int p = 0; p < 2; ++p)
                ldsm_x4(bf[2 * p][0], bf[2 * p][1], bf[2 * p + 1][0], bf[2 * p + 1][1],
                        stage + bLdOff + (uint32_t)(p * 16 * SSTRIDE + kp * 32));
            #pragma unroll
            for (int i = 0; i < 4; ++i)
                #pragma unroll
                for (int j = 0; j < 4; ++j)
                    mma_s8(acc[i][j], af[i], bf[j]);
        }
    }

    // ---- minimal tail: store raw int32 accumulators (epilogue kernel finishes) ----
    #pragma unroll
    for (int i = 0; i < 4; ++i) {
        const int row0 = cta_m + wm * 64 + i * 16 + group;
        #pragma unroll
        for (int j = 0; j < 4; ++j) {
            const int col0 = cta_n + wn * 32 + j * 8 + tg * 2;
            #pragma unroll
            for (int h = 0; h < 2; ++h) {
                const int r = row0 + h * 8;
                int2 v;
                v.x = acc[i][j][h * 2 + 0];
                v.y = acc[i][j][h * 2 + 1];
                *reinterpret_cast<int2*>(outI + (size_t)r * N_DIM + col0) = v;
            }
        }
    }
}

// ---- separate epilogue: in-place dequant + bias + exact GeLU + requant -> f32 ----
__global__ __launch_bounds__(256)
void epilogue_kernel(float* __restrict__ out,
                     const float* __restrict__ bias,
                     const float* __restrict__ aP,
                     const float* __restrict__ bP)
{
    const size_t i = (size_t)blockIdx.x * blockDim.x + threadIdx.x;  // 4 elems each
    const int4 v = reinterpret_cast<const int4*>(out)[i];

    const int col0 = (int)(i & (size_t)(N_DIM / 4 - 1)) * 4;
    const float4 bv4 = *reinterpret_cast<const float4*>(bias + col0);

    const float a = *aP;
    const float b = *bP;
    const float INV_SQRT2 = 0.7071067811865475f;

    float y[4];
    y[0] = fmaf(a, (float)v.x, bv4.x);
    y[1] = fmaf(a, (float)v.y, bv4.y);
    y[2] = fmaf(a, (float)v.z, bv4.z);
    y[3] = fmaf(a, (float)v.w, bv4.w);

    float4 res;
    float* rp = &res.x;
    #pragma unroll
    for (int t = 0; t < 4; ++t) {
        float g = 0.5f * y[t] * (1.0f + erff(y[t] * INV_SQRT2));
        int q = __float2int_rn(g * b);
        q = min(127, max(-128, q));
        rp[t] = (float)q;
    }
    reinterpret_cast<float4*>(out)[i] = res;
}

extern "C" void kernel_launch(void* const* d_in, const int* in_sizes, int n_in,
                              void* d_out, int out_size) {
    // Order-independent input resolution by element count:
    //   x: 8192*4096 (int32-promoted int8), weight: 4096*4096 (int32-promoted int8),
    //   bias: 4096 (f32), a: first size-1 scalar, b: second.
    const int*   X32  = nullptr;
    const int*   W32  = nullptr;
    const float* bias = nullptr;
    const float* a    = nullptr;
    const float* b    = nullptr;
    for (int i = 0; i < n_in; ++i) {
        const int sz = in_sizes[i];
        if (sz == M_DIM * K_DIM)           X32  = (const int*)d_in[i];
        else if (sz == N_DIM * K_DIM)      W32  = (const int*)d_in[i];
        else if (sz == N_DIM)              bias = (const float*)d_in[i];
        else if (sz == 1) {
            if (!a) a = (const float*)d_in[i];
            else    b = (const float*)d_in[i];
        }
    }

    // 1) Narrow int32 -> int8 into static scratch (one fused launch).
    convert_kernel<<<(int)((X_VEC + W_VEC) / 256), 256>>>(X32, W32);

    // 2) GEMM -> raw int32 accumulators staged in d_out.
    cudaFuncSetAttribute(w8a8_gemm_kernel,
                         cudaFuncAttributeMaxDynamicSharedMemorySize, SMEM_ALLOC);
    dim3 grid(N_DIM / CTA_N, M_DIM / CTA_M);   // (32, 64)
    w8a8_gemm_kernel<<<grid, 256, SMEM_ALLOC>>>((int*)d_out);

    // 3) In-place epilogue: int32 acc -> quantized value stored as f32.
    epilogue_kernel<<<(M_DIM * N_DIM / 4) / 256, 256>>>((float*)d_out, bias, a, b);
}

// round 17
// speedup vs baseline: 1.0297x; 1.0297x over previous
#include <cuda_runtime.h>
#include <cstdint>

// Problem constants
#define M_DIM 8192
#define N_DIM 4096
#define K_DIM 4096

#define CTA_M 128
#define CTA_N 128
#define CTA_K 128                 // one SMEM stage covers K=128 (4 MMA phases)
#define SSTRIDE 144               // 128B K data + 16B pad -> conflict-free ldmatrix
#define B_OFF (CTA_M * SSTRIDE)   // B tile after A tile within a stage

#define NSTAGES 2
#define STAGE_BYTES ((CTA_M + CTA_N) * SSTRIDE)   // 36864
#define SMEM_ALLOC (NSTAGES * STAGE_BYTES)        // 73728 (2 CTAs/SM)

// Static scratch for int32 -> int8 narrowed operands (allocation-free).
__device__ int8_t g_x8[(size_t)M_DIM * K_DIM];   // 32 MB
__device__ int8_t g_w8[(size_t)N_DIM * K_DIM];   // 16 MB

__device__ __forceinline__ void cp_async16(uint32_t s, const void* g) {
    asm volatile("cp.async.cg.shared.global [%0], [%1], 16;\n" :: "r"(s), "l"(g));
}

__device__ __forceinline__ void ldsm_x4(uint32_t& r0, uint32_t& r1,
                                        uint32_t& r2, uint32_t& r3, uint32_t addr) {
    asm volatile("ldmatrix.sync.aligned.m8n8.x4.shared.b16 {%0,%1,%2,%3}, [%4];"
                 : "=r"(r0), "=r"(r1), "=r"(r2), "=r"(r3) : "r"(addr));
}

__device__ __forceinline__ void mma_s8(int* c, const uint32_t* a, const uint32_t* b) {
    asm volatile(
        "mma.sync.aligned.m16n8k32.row.col.s32.s8.s8.s32 "
        "{%0,%1,%2,%3}, {%4,%5,%6,%7}, {%8,%9}, {%0,%1,%2,%3};\n"
        : "+r"(c[0]), "+r"(c[1]), "+r"(c[2]), "+r"(c[3])
        : "r"(a[0]), "r"(a[1]), "r"(a[2]), "r"(a[3]), "r"(b[0]), "r"(b[1]));
}

// ---- single fused int32 -> int8 narrowing pre-pass ----
__device__ __forceinline__ uint32_t pack4(int4 v) {
    return __byte_perm(__byte_perm((uint32_t)v.x, (uint32_t)v.y, 0x0040),
                       __byte_perm((uint32_t)v.z, (uint32_t)v.w, 0x0040), 0x5410);
}

#define X_VEC ((size_t)M_DIM * K_DIM / 16)   // uint4-stores for X
#define W_VEC ((size_t)N_DIM * K_DIM / 16)   // for W

__global__ __launch_bounds__(256)
void convert_kernel(const int* __restrict__ xs, const int* __restrict__ ws) {
    const size_t i = (size_t)blockIdx.x * blockDim.x + threadIdx.x;  // 16 elems each
    const int* src;
    uint4* dst;
    size_t idx;
    if (i < X_VEC) { src = xs; dst = reinterpret_cast<uint4*>(g_x8); idx = i; }
    else           { src = ws; dst = reinterpret_cast<uint4*>(g_w8); idx = i - X_VEC; }
    const int4* s4 = reinterpret_cast<const int4*>(src) + idx * 4;
    uint4 o;
    o.x = pack4(s4[0]); o.y = pack4(s4[1]); o.z = pack4(s4[2]); o.w = pack4(s4[3]);
    dst[idx] = o;
}

// ---- main GEMM: mma.sync m16n8k32.s8 + ldmatrix, CTA_K=128, 2-stage ----
__global__ __launch_bounds__(256, 2)
void w8a8_gelu_q_kernel(const float* __restrict__ bias,
                        const float* __restrict__ aP,
                        const float* __restrict__ bP,
                        float*       __restrict__ out)
{
    extern __shared__ uint8_t smem[];

    const int8_t* __restrict__ X = g_x8;
    const int8_t* __restrict__ W = g_w8;

    const int tid   = threadIdx.x;
    const int warp  = tid >> 5;
    const int lane  = tid & 31;
    const int group = lane >> 2;   // 0..7
    const int tg    = lane & 3;    // 0..3
    const int wm    = warp >> 2;   // 0..1  (64 rows of M each)
    const int wn    = warp & 3;    // 0..3  (32 cols of N each)

    const int cta_n = blockIdx.x * CTA_N;
    const int cta_m = blockIdx.y * CTA_M;

    // Global-load mapping: 256 threads x 4 chunks cover 128 rows x 8 x 16B.
    // chunk c = tid + 256*i: row = (tid>>3) + 32*i, 16B-slot = tid&7 (same all i).
    const int lrow = tid >> 3;        // 0..31
    const int lc16 = (tid & 7) << 4;  // byte offset within row: 0..112

    const int8_t* gA = X + (size_t)(cta_m + lrow) * K_DIM + lc16;
    const int8_t* gB = W + (size_t)(cta_n + lrow) * K_DIM + lc16;

    const uint32_t sBase = (uint32_t)__cvta_generic_to_shared(smem);
    const uint32_t dAl = (uint32_t)(lrow * SSTRIDE + lc16);
    const uint32_t dBl = (uint32_t)B_OFF + dAl;

    // ldmatrix per-lane offsets (verified fragment layout, rel_err 0.0):
    const uint32_t aLdOff = (uint32_t)((wm * 64 + (lane & 15)) * SSTRIDE
                                       + (lane >> 4) * 16);
    const uint32_t bLdOff = (uint32_t)(B_OFF
                                       + (wn * 32 + ((lane >> 4) & 1) * 8 + (lane & 7)) * SSTRIDE
                                       + ((lane >> 3) & 1) * 16);

    int acc[4][4][4];
    #pragma unroll
    for (int i = 0; i < 4; ++i)
        #pragma unroll
        for (int j = 0; j < 4; ++j)
            #pragma unroll
            for (int r = 0; r < 4; ++r)
                acc[i][j][r] = 0;

    const int KITERS = K_DIM / CTA_K;   // 32

    // ---- prologue: load stage 0 ----
    #pragma unroll
    for (int i = 0; i < 4; ++i) {
        cp_async16(sBase + dAl + (uint32_t)(i * 32 * SSTRIDE), gA + (size_t)(32 * i) * K_DIM);
        cp_async16(sBase + dBl + (uint32_t)(i * 32 * SSTRIDE), gB + (size_t)(32 * i) * K_DIM);
    }
    asm volatile("cp.async.commit_group;\n" ::);

    for (int kit = 0; kit < KITERS; ++kit) {
        // stage kit&1 was committed last; wait for everything outstanding.
        asm volatile("cp.async.wait_group 0;\n" ::);
        // Single barrier: (a) stage kit visible to all warps, (b) all warps done
        // reading stage kit-1 (overwritten by the prefetch below).
        __syncthreads();

        const uint32_t stage = sBase + (uint32_t)((kit & 1) * STAGE_BYTES);

        // prefetch stage kit+1 (overlaps with the 16 MMA-phases below)
        if (kit + 1 < KITERS) {
            const uint32_t st = sBase + (uint32_t)(((kit + 1) & 1) * STAGE_BYTES);
            const int k0 = (kit + 1) * CTA_K;
            #pragma unroll
            for (int i = 0; i < 4; ++i) {
                cp_async16(st + dAl + (uint32_t)(i * 32 * SSTRIDE),
                           gA + (size_t)(32 * i) * K_DIM + k0);
                cp_async16(st + dBl + (uint32_t)(i * 32 * SSTRIDE),
                           gB + (size_t)(32 * i) * K_DIM + k0);
            }
            asm volatile("cp.async.commit_group;\n" ::);
        }

        #pragma unroll
        for (int kp = 0; kp < 4; ++kp) {       // four k=32 phases inside CTA_K=128
            uint32_t af[4][4];
            uint32_t bf[4][2];
            #pragma unroll
            for (int i = 0; i < 4; ++i)
                ldsm_x4(af[i][0], af[i][1], af[i][2], af[i][3],
                        stage + aLdOff + (uint32_t)(i * 16 * SSTRIDE + kp * 32));
            #pragma unroll
            for (int p = 0; p < 2; ++p)
                ldsm_x4(bf[2 * p][0], bf[2 * p][1], bf[2 * p + 1][0], bf[2 * p + 1][1],
                        stage + bLdOff + (uint32_t)(p * 16 * SSTRIDE + kp * 32));
            #pragma unroll
            for (int i = 0; i < 4; ++i)
                #pragma unroll
                for (int j = 0; j < 4; ++j)
                    mma_s8(acc[i][j], af[i], bf[j]);
        }
    }

    // ---- fused epilogue: dequant + bias + exact GeLU + requant; store as f32 ----
    const float a = *aP;
    const float b = *bP;
    const float INV_SQRT2 = 0.7071067811865475f;

    #pragma unroll
    for (int i = 0; i < 4; ++i) {
        const int row0 = cta_m + wm * 64 + i * 16 + group;
        #pragma unroll
        for (int j = 0; j < 4; ++j) {
            const int col0 = cta_n + wn * 32 + j * 8 + tg * 2;
            const float bias0 = bias[col0];
            const float bias1 = bias[col0 + 1];
            #pragma unroll
            for (int h = 0; h < 2; ++h) {     // h=0: c0,c1 (row); h=1: c2,c3 (row+8)
                const int r = row0 + h * 8;
                float y0 = fmaf(a, (float)acc[i][j][h * 2 + 0], bias0);
                float y1 = fmaf(a, (float)acc[i][j][h * 2 + 1], bias1);
                y0 = 0.5f * y0 * (1.0f + erff(y0 * INV_SQRT2));
                y1 = 0.5f * y1 * (1.0f + erff(y1 * INV_SQRT2));
                int q0 = __float2int_rn(y0 * b);
                int q1 = __float2int_rn(y1 * b);
                q0 = min(127, max(-128, q0));
                q1 = min(127, max(-128, q1));
                float2 pk;
                pk.x = (float)q0;
                pk.y = (float)q1;
                *reinterpret_cast<float2*>(out + (size_t)r * N_DIM + col0) = pk;
            }
        }
    }
}

extern "C" void kernel_launch(void* const* d_in, const int* in_sizes, int n_in,
                              void* d_out, int out_size) {
    // Order-independent input resolution by element count:
    //   x: 8192*4096 (int32-promoted int8), weight: 4096*4096 (int32-promoted int8),
    //   bias: 4096 (f32), a: first size-1 scalar, b: second.
    const int*   X32  = nullptr;
    const int*   W32  = nullptr;
    const float* bias = nullptr;
    const float* a    = nullptr;
    const float* b    = nullptr;
    for (int i = 0; i < n_in; ++i) {
        const int sz = in_sizes[i];
        if (sz == M_DIM * K_DIM)           X32  = (const int*)d_in[i];
        else if (sz == N_DIM * K_DIM)      W32  = (const int*)d_in[i];
        else if (sz == N_DIM)              bias = (const float*)d_in[i];
        else if (sz == 1) {
            if (!a) a = (const float*)d_in[i];
            else    b = (const float*)d_in[i];
        }
    }

    // 1) Narrow int32 -> int8 into static scratch (one fused launch).
    convert_kernel<<<(int)((X_VEC + W_VEC) / 256), 256>>>(X32, W32);

    // 2) Fused GEMM + epilogue.
    cudaFuncSetAttribute(w8a8_gelu_q_kernel,
                         cudaFuncAttributeMaxDynamicSharedMemorySize, SMEM_ALLOC);
    dim3 grid(N_DIM / CTA_N, M_DIM / CTA_M);   // (32, 64)
    w8a8_gelu_q_kernel<<<grid, 256, SMEM_ALLOC>>>(bias, a, b, (float*)d_out);
}